// round 14
// baseline (speedup 1.0000x reference)
#include <cuda_runtime.h>
#include <math.h>

#define BB 256
#define N_SV 64
#define N_TRK 512
#define N_PFC 512
#define KNN 8
#define HH 32

typedef unsigned long long u64;
typedef unsigned int u32;

// ---------------- scratch (static device arrays; no allocation) -------------
__device__ float g_sv [BB * N_SV  * HH];
__device__ float g_trk[BB * N_TRK * HH];
__device__ float g_pfc[BB * N_PFC * HH];
__device__ float g_U  [BB * N_TRK * HH];
__device__ float g_V  [BB * N_PFC * HH];
__device__ float g_V1 [BB * N_SV  * HH];
__device__ float g_f1 [BB * N_TRK * HH];
__device__ float g_f2 [BB * N_TRK * HH];
__device__ float g_f3 [BB * N_TRK * HH];
__device__ float g_sqV1[BB * N_SV ];
__device__ float g_sqV [BB * N_PFC];
__device__ float g_sqU [BB * N_TRK];

__device__ __forceinline__ float eluf(float x) {
    return x > 0.f ? x : (expf(x) - 1.f);
}

__device__ __forceinline__ void tf32split(float x, u32& h, u32& l) {
    asm("cvt.rna.tf32.f32 %0, %1;" : "=r"(h) : "f"(x));
    float r = x - __uint_as_float(h);
    asm("cvt.rna.tf32.f32 %0, %1;" : "=r"(l) : "f"(r));
}

__device__ __forceinline__ void mma_tf32(float& c0, float& c1, float& c2, float& c3,
                                         u32 a0, u32 a1, u32 a2, u32 a3,
                                         u32 b0, u32 b1)
{
    asm volatile(
        "mma.sync.aligned.m16n8k8.row.col.f32.tf32.tf32.f32 "
        "{%0,%1,%2,%3}, {%4,%5,%6,%7}, {%8,%9}, {%0,%1,%2,%3};"
        : "+f"(c0), "+f"(c1), "+f"(c2), "+f"(c3)
        : "r"(a0), "r"(a1), "r"(a2), "r"(a3), "r"(b0), "r"(b1));
}

// BRANCHLESS insert of c into sorted ascending sel[0..7], dropping the max.
// If c >= sel[7] this is a no-op. No divergent control flow.
__device__ __forceinline__ void ins_u64(u64 (&sel)[8], u64 c)
{
    u64 cur = c;
#pragma unroll
    for (int p = 0; p < 8; ++p) {
        u64 lo = (sel[p] < cur) ? sel[p] : cur;
        u64 hi = (sel[p] < cur) ? cur : sel[p];
        sel[p] = lo;
        cur = hi;
    }
}

// ================= fused encoder: 2-layer MLP, 128 nodes/block ==============
template <int FIN>
__device__ __forceinline__ void encode_body(
    const float* __restrict__ x,
    const float* __restrict__ W1, const float* __restrict__ b1,
    const float* __restrict__ W2, const float* __restrict__ b2,
    float* __restrict__ out, int blk,
    float* w1s, float* w2s, float* b1s, float* b2s)
{
    int tid = threadIdx.x;
    for (int i = tid; i < FIN * 32; i += 256) w1s[i] = W1[i];
    for (int i = tid; i < 1024;     i += 256) w2s[i] = W2[i];
    if (tid < 32) { b1s[tid] = b1[tid]; b2s[tid] = b2[tid]; }
    __syncthreads();

    int lane = tid & 31, wid = tid >> 5;

#pragma unroll
    for (int it = 0; it < 4; ++it) {
        int nb = blk * 128 + it * 32 + wid * 4;

        float xv0 = (lane < FIN) ? x[(size_t)(nb + 0) * FIN + lane] : 0.f;
        float xv1 = (lane < FIN) ? x[(size_t)(nb + 1) * FIN + lane] : 0.f;
        float xv2 = (lane < FIN) ? x[(size_t)(nb + 2) * FIN + lane] : 0.f;
        float xv3 = (lane < FIN) ? x[(size_t)(nb + 3) * FIN + lane] : 0.f;

        float h0 = b1s[lane], h1 = h0, h2 = h0, h3 = h0;
#pragma unroll
        for (int i = 0; i < FIN; ++i) {
            float w = w1s[i * 32 + lane];
            h0 = fmaf(__shfl_sync(0xffffffffu, xv0, i), w, h0);
            h1 = fmaf(__shfl_sync(0xffffffffu, xv1, i), w, h1);
            h2 = fmaf(__shfl_sync(0xffffffffu, xv2, i), w, h2);
            h3 = fmaf(__shfl_sync(0xffffffffu, xv3, i), w, h3);
        }
        h0 = eluf(h0); h1 = eluf(h1); h2 = eluf(h2); h3 = eluf(h3);

        float o0 = b2s[lane], o1 = o0, o2 = o0, o3 = o0;
#pragma unroll
        for (int i = 0; i < 32; ++i) {
            float w = w2s[i * 32 + lane];
            o0 = fmaf(__shfl_sync(0xffffffffu, h0, i), w, o0);
            o1 = fmaf(__shfl_sync(0xffffffffu, h1, i), w, o1);
            o2 = fmaf(__shfl_sync(0xffffffffu, h2, i), w, o2);
            o3 = fmaf(__shfl_sync(0xffffffffu, h3, i), w, o3);
        }
        out[(size_t)(nb + 0) * 32 + lane] = eluf(o0);
        out[(size_t)(nb + 1) * 32 + lane] = eluf(o1);
        out[(size_t)(nb + 2) * 32 + lane] = eluf(o2);
        out[(size_t)(nb + 3) * 32 + lane] = eluf(o3);
    }
}

__global__ void __launch_bounds__(256) encode_all_k(
    const float* x_sv, const float* x_trk, const float* x_pfc,
    const float* svW1, const float* svb1, const float* svW2, const float* svb2,
    const float* tkW1, const float* tkb1, const float* tkW2, const float* tkb2,
    const float* pfW1, const float* pfb1, const float* pfW2, const float* pfb2,
    float* o_sv, float* o_trk, float* o_pfc)
{
    __shared__ float w1s[32 * 32];
    __shared__ float w2s[32 * 32];
    __shared__ float b1s[32], b2s[32];
    int b = blockIdx.x;
    if (b < 128)
        encode_body<14>(x_sv, svW1, svb1, svW2, svb2, o_sv, b, w1s, w2s, b1s, b2s);
    else if (b < 1152)
        encode_body<30>(x_trk, tkW1, tkb1, tkW2, tkb2, o_trk, b - 128, w1s, w2s, b1s, b2s);
    else
        encode_body<10>(x_pfc, pfW1, pfb1, pfW2, pfb2, o_pfc, b - 1152, w1s, w2s, b1s, b2s);
}

// ====== fused 32x32 linear (mode 0: (Wa-Wb)+b, mode 1: Wb) + sq output ======
__device__ __forceinline__ void lin_body(
    const float* __restrict__ in, float* __restrict__ out,
    float* __restrict__ sqout, int blk, int mode,
    const float* __restrict__ convW, const float* __restrict__ convB,
    float* ws, float* bs)
{
    int tid = threadIdx.x;
    for (int i = tid; i < 1024; i += 256)
        ws[i] = (mode == 0) ? (convW[i] - convW[1024 + i]) : convW[1024 + i];
    if (tid < 32) bs[tid] = (mode == 0) ? convB[tid] : 0.f;
    __syncthreads();

    int lane = tid & 31, wid = tid >> 5;

#pragma unroll
    for (int it = 0; it < 4; ++it) {
        int nb = blk * 128 + it * 32 + wid * 4;

        float xv0 = in[(size_t)(nb + 0) * 32 + lane];
        float xv1 = in[(size_t)(nb + 1) * 32 + lane];
        float xv2 = in[(size_t)(nb + 2) * 32 + lane];
        float xv3 = in[(size_t)(nb + 3) * 32 + lane];

        float s0 = xv0 * xv0, s1 = xv1 * xv1, s2 = xv2 * xv2, s3 = xv3 * xv3;
#pragma unroll
        for (int o = 16; o; o >>= 1) {
            s0 += __shfl_xor_sync(0xffffffffu, s0, o);
            s1 += __shfl_xor_sync(0xffffffffu, s1, o);
            s2 += __shfl_xor_sync(0xffffffffu, s2, o);
            s3 += __shfl_xor_sync(0xffffffffu, s3, o);
        }
        if (lane == 0) {
            sqout[nb + 0] = s0; sqout[nb + 1] = s1;
            sqout[nb + 2] = s2; sqout[nb + 3] = s3;
        }

        float o0 = bs[lane], o1 = o0, o2 = o0, o3 = o0;
#pragma unroll
        for (int i = 0; i < 32; ++i) {
            float w = ws[i * 32 + lane];
            o0 = fmaf(__shfl_sync(0xffffffffu, xv0, i), w, o0);
            o1 = fmaf(__shfl_sync(0xffffffffu, xv1, i), w, o1);
            o2 = fmaf(__shfl_sync(0xffffffffu, xv2, i), w, o2);
            o3 = fmaf(__shfl_sync(0xffffffffu, xv3, i), w, o3);
        }
        out[(size_t)(nb + 0) * 32 + lane] = o0;
        out[(size_t)(nb + 1) * 32 + lane] = o1;
        out[(size_t)(nb + 2) * 32 + lane] = o2;
        out[(size_t)(nb + 3) * 32 + lane] = o3;
    }
}

__global__ void __launch_bounds__(256) lin_all_k(
    const float* sv, const float* trk, const float* pfc,
    float* V1, float* U, float* V,
    float* sqV1, float* sqU, float* sqV,
    const float* convW, const float* convB)
{
    __shared__ float ws[1024];
    __shared__ float bs[32];
    int b = blockIdx.x;
    if (b < 128)        lin_body(sv,  V1, sqV1, b,        1, convW, convB, ws, bs);
    else if (b < 1152)  lin_body(trk, U,  sqU,  b - 128,  0, convW, convB, ws, bs);
    else                lin_body(pfc, V,  sqV,  b - 1152, 1, convW, convB, ws, bs);
}

__global__ void __launch_bounds__(256) lin2_k(
    const float* f1, const float* f2, float* V, float* U,
    float* sqV, float* sqU,
    const float* convW, const float* convB)
{
    __shared__ float ws[1024];
    __shared__ float bs[32];
    int b = blockIdx.x;
    if (b < 1024) lin_body(f1, V, sqV, b,        1, convW, convB, ws, bs);
    else          lin_body(f2, U, sqU, b - 1024, 0, convW, convB, ws, bs);
}

// ================= kNN: mma scoring + running-tau selection =================
// 4 blocks/event (128 dsts), 256 threads = 8 warps, ONE m16 tile/warp.
// Scores in [128][72] rows, halves at float-offsets 0 / 36 (each 32 scores +
// 4 pad) -> selection thread reads its half as 8 aligned LDS.128, bank-free.
// Threshold = running min over chunks of packed tau (valid for the whole scan:
// any global top-8 member is < tau_c for EVERY chunk c), optionally tightened
// by sel[7]. Appends are predicated stores; flush only on capacity vote; all
// inserts use the branchless min/max sweep (no divergent sort).
#define CH       64
#define SSTRIDE  72
#define C4STRIDE 66      /* float4 units per c4sel slot */
#define CAPK     8
#define SM_SCORES 0
#define SM_HILO  36864   /* 16 slots x 66 float4 = 16896 B */
#define SM_SQS   53760
#define SM_SDS   54016
#define SM_TAU   54528
#define SM_BUF   55040
#define KNN_SMEM (SM_BUF + 256 * CAPK * 8)   /* 71424 */

__device__ __forceinline__ void flush_u64(const u64* mybuf, int& cnt, u64 (&sel)[8])
{
    for (int i = 0; i < cnt; ++i)
        ins_u64(sel, mybuf[i]);
    cnt = 0;
}

__global__ void __launch_bounds__(256, 3) knn_k(
                      const float* __restrict__ src_enc,
                      const float* __restrict__ dst_enc,
                      const float* __restrict__ sq_src,
                      const float* __restrict__ sq_dst,
                      const float* __restrict__ V,
                      const float* __restrict__ U,
                      float* __restrict__ out, int Ns)
{
    extern __shared__ char smraw[];
    float*  scores = (float*)(smraw + SM_SCORES);  // [128][72]
    float4* hi4    = (float4*)(smraw + SM_HILO);   // [8][66] hi, then [8][66] lo
    float*  hifl   = (float*)(smraw + SM_HILO);
    float*  sqs    = (float*)(smraw + SM_SQS);     // [64]
    float*  sds    = (float*)(smraw + SM_SDS);     // [128]
    float*  tau    = (float*)(smraw + SM_TAU);     // [128]
    u64*    buf    = (u64*)(smraw + SM_BUF);       // [256][CAPK]
    int*    idxs   = (int*)(smraw + SM_HILO);      // overlay after last MMA

    int tid  = threadIdx.x;
    int lane = tid & 31;
    int w    = tid >> 5;          // 0..7
    int e    = blockIdx.x >> 2;
    int quar = blockIdx.x & 3;
    int g    = lane >> 2;         // 0..7
    int c4   = lane & 3;          // 0..3

    const float* sbase = src_enc + (size_t)e * Ns * 32;
    int dstblk = quar * 128;
    const float* dbase = dst_enc + ((size_t)e * 512 + dstblk + w * 16) * 32;

    if (tid < 128) sds[tid] = sq_dst[(size_t)e * 512 + dstblk + tid];

    // ---- A fragments: one m16 tile (16 dsts) per warp ----
    u32 ahi[16], alo[16];
#pragma unroll
    for (int j = 0; j < 4; ++j) {
        int k = 8 * j + c4;
        tf32split(dbase[g * 32 + k],           ahi[4*j+0], alo[4*j+0]);
        tf32split(dbase[(g + 8) * 32 + k],     ahi[4*j+1], alo[4*j+1]);
        tf32split(dbase[g * 32 + k + 4],       ahi[4*j+2], alo[4*j+2]);
        tf32split(dbase[(g + 8) * 32 + k + 4], ahi[4*j+3], alo[4*j+3]);
    }
    __syncthreads();

    float sd0 = sds[w * 16 + g];
    float sd1 = sds[w * 16 + 8 + g];
    int rowA0 = (w * 16 + g) * SSTRIDE;
    int rowA1 = (w * 16 + 8 + g) * SSTRIDE;

    int myd = tid >> 1;
    int hh  = tid & 1;
    int selbase = myd * SSTRIDE + hh * 36;   // contiguous half-row, 16B aligned

    const float4* bhA = hi4 + (size_t)c4 * C4STRIDE;
    const float4* bhB = hi4 + (size_t)(c4 + 4) * C4STRIDE;
    const float4* blA = bhA + 8 * C4STRIDE;
    const float4* blB = bhB + 8 * C4STRIDE;

    u64 sel[8];
#pragma unroll
    for (int k = 0; k < 8; ++k) sel[k] = ~0ull;
    int cnt = 0;
    u64 trun = ~0ull;                        // running packed tau bound
    u64* mybuf = buf + (size_t)tid * CAPK;
    unsigned buf_sa = (unsigned)__cvta_generic_to_shared(mybuf);

    int stg = (lane & 7) * (C4STRIDE * 4) + (lane >> 3);

    int nch = (Ns + CH - 1) / CH;
    for (int ch = 0; ch < nch; ++ch) {
        int cbase = ch * CH;

        __syncthreads();
        // ---- stage 64 srcs into [c4sel][sl][j] layout ----
        for (int sl = w; sl < CH; sl += 8) {
            float x = sbase[(size_t)(cbase + sl) * 32 + lane];
            u32 h, l;
            tf32split(x, h, l);
            hifl[stg + sl * 4]                    = __uint_as_float(h);
            hifl[stg + sl * 4 + 8 * C4STRIDE * 4] = __uint_as_float(l);
        }
        if (tid < CH) sqs[tid] = sq_src[(size_t)e * Ns + cbase + tid];
        __syncthreads();

        // ---- MMA + epilogue: 3 independent chains, scores + subset minima --
        float mn00 = 3.4e38f, mn01 = 3.4e38f, mn10 = 3.4e38f, mn11 = 3.4e38f;
#pragma unroll
        for (int st = 0; st < CH / 8; ++st) {
            int sl0 = st << 3;
            int fidx = sl0 + g;
            float4 H0 = bhA[fidx];
            float4 H1 = bhB[fidx];
            float4 L0 = blA[fidx];
            float4 L1 = blB[fidx];

            float p0 = 0.f, p1 = 0.f, p2 = 0.f, p3 = 0.f;
            float q0 = 0.f, q1 = 0.f, q2 = 0.f, q3 = 0.f;
            float r0 = 0.f, r1 = 0.f, r2 = 0.f, r3 = 0.f;

            mma_tf32(p0, p1, p2, p3, ahi[0],  ahi[1],  ahi[2],  ahi[3],
                     __float_as_uint(H0.x), __float_as_uint(H1.x));
            mma_tf32(p0, p1, p2, p3, ahi[4],  ahi[5],  ahi[6],  ahi[7],
                     __float_as_uint(H0.y), __float_as_uint(H1.y));
            mma_tf32(p0, p1, p2, p3, ahi[8],  ahi[9],  ahi[10], ahi[11],
                     __float_as_uint(H0.z), __float_as_uint(H1.z));
            mma_tf32(p0, p1, p2, p3, ahi[12], ahi[13], ahi[14], ahi[15],
                     __float_as_uint(H0.w), __float_as_uint(H1.w));
            mma_tf32(q0, q1, q2, q3, ahi[0],  ahi[1],  ahi[2],  ahi[3],
                     __float_as_uint(L0.x), __float_as_uint(L1.x));
            mma_tf32(q0, q1, q2, q3, ahi[4],  ahi[5],  ahi[6],  ahi[7],
                     __float_as_uint(L0.y), __float_as_uint(L1.y));
            mma_tf32(q0, q1, q2, q3, ahi[8],  ahi[9],  ahi[10], ahi[11],
                     __float_as_uint(L0.z), __float_as_uint(L1.z));
            mma_tf32(q0, q1, q2, q3, ahi[12], ahi[13], ahi[14], ahi[15],
                     __float_as_uint(L0.w), __float_as_uint(L1.w));
            mma_tf32(r0, r1, r2, r3, alo[0],  alo[1],  alo[2],  alo[3],
                     __float_as_uint(H0.x), __float_as_uint(H1.x));
            mma_tf32(r0, r1, r2, r3, alo[4],  alo[5],  alo[6],  alo[7],
                     __float_as_uint(H0.y), __float_as_uint(H1.y));
            mma_tf32(r0, r1, r2, r3, alo[8],  alo[9],  alo[10], alo[11],
                     __float_as_uint(H0.z), __float_as_uint(H1.z));
            mma_tf32(r0, r1, r2, r3, alo[12], alo[13], alo[14], alo[15],
                     __float_as_uint(H0.w), __float_as_uint(H1.w));

            float a0 = p0 + (q0 + r0);
            float a1 = p1 + (q1 + r1);
            float a2 = p2 + (q2 + r2);
            float a3 = p3 + (q3 + r3);

            float2 sqp = *(const float2*)(sqs + sl0 + 2 * c4);
            int scol = sl0 + 2 * c4 + ((st >= 4) ? 4 : 0);   // half pad skip
            float d00 = fmaxf(fmaf(-2.f, a0, sd0 + sqp.x), 0.f);
            float d01 = fmaxf(fmaf(-2.f, a1, sd0 + sqp.y), 0.f);
            float d10 = fmaxf(fmaf(-2.f, a2, sd1 + sqp.x), 0.f);
            float d11 = fmaxf(fmaf(-2.f, a3, sd1 + sqp.y), 0.f);
            mn00 = fminf(mn00, d00); mn01 = fminf(mn01, d01);
            mn10 = fminf(mn10, d10); mn11 = fminf(mn11, d11);
            *(float2*)(scores + rowA0 + scol) = make_float2(d00, d01);
            *(float2*)(scores + rowA1 + scol) = make_float2(d10, d11);
        }
        {
            float m0 = fmaxf(mn00, mn01);
            m0 = fmaxf(m0, __shfl_xor_sync(0xffffffffu, m0, 1));
            m0 = fmaxf(m0, __shfl_xor_sync(0xffffffffu, m0, 2));
            float m1 = fmaxf(mn10, mn11);
            m1 = fmaxf(m1, __shfl_xor_sync(0xffffffffu, m1, 1));
            m1 = fmaxf(m1, __shfl_xor_sync(0xffffffffu, m1, 2));
            if (c4 == 0) {
                tau[w * 16 + g]     = m0;
                tau[w * 16 + 8 + g] = m1;
            }
        }
        __syncthreads();

        // ---- selection: running-tau fixed threshold, predicated appends ----
        {
            u64 tu = ((u64)(__float_as_uint(tau[myd]) + 1u)) << 32;
            trun = (tu < trun) ? tu : trun;               // running chunk bound
            u64 t = (trun < sel[7]) ? trun : sel[7];

            int ibase = cbase + hh * 32;
#pragma unroll
            for (int q8 = 0; q8 < 8; ++q8) {
                float4 v = *(const float4*)(scores + selbase + 4 * q8);
                u64 p0 = ((u64)__float_as_uint(v.x) << 32) | (u32)(ibase + 4 * q8);
                u64 p1 = ((u64)__float_as_uint(v.y) << 32) | (u32)(ibase + 4 * q8 + 1);
                u64 p2 = ((u64)__float_as_uint(v.z) << 32) | (u32)(ibase + 4 * q8 + 2);
                u64 p3 = ((u64)__float_as_uint(v.w) << 32) | (u32)(ibase + 4 * q8 + 3);

                asm volatile("{.reg .pred p; setp.lt.u64 p, %1, %2; @p st.shared.b64 [%0], %1;}"
                    :: "r"(buf_sa + (unsigned)cnt * 8u), "l"(p0), "l"(t) : "memory");
                cnt += (p0 < t) ? 1 : 0;
                asm volatile("{.reg .pred p; setp.lt.u64 p, %1, %2; @p st.shared.b64 [%0], %1;}"
                    :: "r"(buf_sa + (unsigned)cnt * 8u), "l"(p1), "l"(t) : "memory");
                cnt += (p1 < t) ? 1 : 0;
                asm volatile("{.reg .pred p; setp.lt.u64 p, %1, %2; @p st.shared.b64 [%0], %1;}"
                    :: "r"(buf_sa + (unsigned)cnt * 8u), "l"(p2), "l"(t) : "memory");
                cnt += (p2 < t) ? 1 : 0;
                asm volatile("{.reg .pred p; setp.lt.u64 p, %1, %2; @p st.shared.b64 [%0], %1;}"
                    :: "r"(buf_sa + (unsigned)cnt * 8u), "l"(p3), "l"(t) : "memory");
                cnt += (p3 < t) ? 1 : 0;

                // capacity-safety flush (<=4 appends per q8 step)
                if (__any_sync(0xffffffffu, cnt >= CAPK - 4)) {
                    flush_u64(mybuf, cnt, sel);
                    u64 t2 = (trun < sel[7]) ? trun : sel[7];
                    t = t2;
                }
            }
        }
    }
    flush_u64(mybuf, cnt, sel);

    // ---- dump per-thread lists, 2-way exact merge ----
#pragma unroll
    for (int k = 0; k < 8; ++k) mybuf[k] = sel[k];
    __syncthreads();

    if (tid < 128) {
        u64 m[8];
        const u64* l0 = buf + (size_t)(2 * tid) * CAPK;
        const u64* l1 = buf + (size_t)(2 * tid + 1) * CAPK;
#pragma unroll
        for (int k = 0; k < 8; ++k) m[k] = l0[k];
#pragma unroll
        for (int k = 0; k < 8; ++k)
            ins_u64(m, l1[k]);
#pragma unroll
        for (int k = 0; k < 8; ++k)
            idxs[tid * 8 + k] = (int)(u32)m[k];
    }
    __syncthreads();

    // ---- aggregation: warp per dst, coalesced V gathers ----
    const float* Ve = V + (size_t)e * Ns * 32;
    for (int dd = w; dd < 128; dd += 8) {
        int dg = e * 512 + dstblk + dd;
        float mx = -3.4e38f;
#pragma unroll
        for (int k = 0; k < KNN; ++k) {
            int s = idxs[dd * 8 + k];
            mx = fmaxf(mx, Ve[s * 32 + lane]);
        }
        out[(size_t)dg * 32 + lane] = eluf(U[(size_t)dg * 32 + lane] + mx);
    }
}

// ---------------- mean pool + head MLP + sigmoid -----------------------------
__global__ void pool_k(const float* __restrict__ f3,
                       const float* __restrict__ W1, const float* __restrict__ b1,
                       const float* __restrict__ W2, const float* __restrict__ b2,
                       float* __restrict__ out, int out_size)
{
    int e = blockIdx.x;
    int tid = threadIdx.x;
    int j = tid & 31, g = tid >> 5;
    const float* base = f3 + (size_t)e * 512 * 32;
    float acc = 0.f;
    for (int r = g; r < 512; r += 8) acc += base[r * 32 + j];
    __shared__ float red[8][32];
    red[g][j] = acc;
    __syncthreads();
    if (tid < 32) {
        float s = 0.f;
#pragma unroll
        for (int gg = 0; gg < 8; ++gg) s += red[gg][tid];
        float pooled = s * (1.f / 512.f);
        float h = b1[tid];
#pragma unroll
        for (int i = 0; i < 32; ++i)
            h = fmaf(__shfl_sync(0xffffffffu, pooled, i), W1[i * 32 + tid], h);
        h = eluf(h);
        float t = h * W2[tid];
#pragma unroll
        for (int o = 16; o; o >>= 1) t += __shfl_down_sync(0xffffffffu, t, o);
        if (tid == 0) {
            float prob = 1.f / (1.f + expf(-(t + b2[0])));
            out[e] = prob;
            if (out_size == 2 * BB) out[BB + e] = (float)e;
            else if (out_size == 3 * BB) ((long long*)(out + BB))[e] = (long long)e;
        }
    }
}

// ---------------- launch ------------------------------------------------------
extern "C" void kernel_launch(void* const* d_in, const int* in_sizes, int n_in,
                              void* d_out, int out_size)
{
    const float* x_sv   = (const float*)d_in[0];
    const float* x_trk  = (const float*)d_in[1];
    const float* x_pfc  = (const float*)d_in[2];
    const float* sv_W1  = (const float*)d_in[6];
    const float* sv_b1  = (const float*)d_in[7];
    const float* sv_W2  = (const float*)d_in[8];
    const float* sv_b2  = (const float*)d_in[9];
    const float* trk_W1 = (const float*)d_in[10];
    const float* trk_b1 = (const float*)d_in[11];
    const float* trk_W2 = (const float*)d_in[12];
    const float* trk_b2 = (const float*)d_in[13];
    const float* pfc_W1 = (const float*)d_in[14];
    const float* pfc_b1 = (const float*)d_in[15];
    const float* pfc_W2 = (const float*)d_in[16];
    const float* pfc_b2 = (const float*)d_in[17];
    const float* conv_W = (const float*)d_in[18];
    const float* conv_b = (const float*)d_in[19];
    const float* out_W1 = (const float*)d_in[20];
    const float* out_b1 = (const float*)d_in[21];
    const float* out_W2 = (const float*)d_in[22];
    const float* out_b2 = (const float*)d_in[23];
    float* out = (float*)d_out;

    float *sv, *trk, *pfc, *U, *V, *V1, *f1, *f2, *f3, *sqV1, *sqV, *sqU;
    cudaGetSymbolAddress((void**)&sv,  g_sv);
    cudaGetSymbolAddress((void**)&trk, g_trk);
    cudaGetSymbolAddress((void**)&pfc, g_pfc);
    cudaGetSymbolAddress((void**)&U,   g_U);
    cudaGetSymbolAddress((void**)&V,   g_V);
    cudaGetSymbolAddress((void**)&V1,  g_V1);
    cudaGetSymbolAddress((void**)&f1,  g_f1);
    cudaGetSymbolAddress((void**)&f2,  g_f2);
    cudaGetSymbolAddress((void**)&f3,  g_f3);
    cudaGetSymbolAddress((void**)&sqV1, g_sqV1);
    cudaGetSymbolAddress((void**)&sqV,  g_sqV);
    cudaGetSymbolAddress((void**)&sqU,  g_sqU);

    cudaFuncSetAttribute(knn_k, cudaFuncAttributeMaxDynamicSharedMemorySize, KNN_SMEM);

    encode_all_k<<<2176, 256>>>(x_sv, x_trk, x_pfc,
                                sv_W1, sv_b1, sv_W2, sv_b2,
                                trk_W1, trk_b1, trk_W2, trk_b2,
                                pfc_W1, pfc_b1, pfc_W2, pfc_b2,
                                sv, trk, pfc);
    lin_all_k<<<2176, 256>>>(sv, trk, pfc, V1, U, V, sqV1, sqU, sqV, conv_W, conv_b);
    knn_k<<<BB * 4, 256, KNN_SMEM>>>(sv,  trk, sqV1, sqU, V1, U, f1, N_SV);
    knn_k<<<BB * 4, 256, KNN_SMEM>>>(pfc, trk, sqV,  sqU, V,  U, f2, N_PFC);
    lin2_k<<<2048, 256>>>(f1, f2, V, U, sqV, sqU, conv_W, conv_b);
    knn_k<<<BB * 4, 256, KNN_SMEM>>>(f1, f2, sqV, sqU, V, U, f3, N_TRK);
    pool_k<<<BB, 256>>>(f3, out_W1, out_b1, out_W2, out_b2, out, out_size);
}

// round 15
// speedup vs baseline: 1.0831x; 1.0831x over previous
#include <cuda_runtime.h>
#include <math.h>

#define BB 256
#define N_SV 64
#define N_TRK 512
#define N_PFC 512
#define KNN 8
#define HH 32

typedef unsigned long long u64;
typedef unsigned int u32;

// ---------------- scratch (static device arrays; no allocation) -------------
__device__ float g_sv [BB * N_SV  * HH];
__device__ float g_trk[BB * N_TRK * HH];
__device__ float g_pfc[BB * N_PFC * HH];
__device__ float g_U  [BB * N_TRK * HH];
__device__ float g_V  [BB * N_PFC * HH];
__device__ float g_V1 [BB * N_SV  * HH];
__device__ float g_f1 [BB * N_TRK * HH];
__device__ float g_f2 [BB * N_TRK * HH];
__device__ float g_f3 [BB * N_TRK * HH];
__device__ float g_sqV1[BB * N_SV ];
__device__ float g_sqV [BB * N_PFC];
__device__ float g_sqU [BB * N_TRK];

__device__ __forceinline__ float eluf(float x) {
    return x > 0.f ? x : (expf(x) - 1.f);
}

__device__ __forceinline__ void tf32split(float x, u32& h, u32& l) {
    asm("cvt.rna.tf32.f32 %0, %1;" : "=r"(h) : "f"(x));
    float r = x - __uint_as_float(h);
    asm("cvt.rna.tf32.f32 %0, %1;" : "=r"(l) : "f"(r));
}

__device__ __forceinline__ void mma_tf32(float& c0, float& c1, float& c2, float& c3,
                                         u32 a0, u32 a1, u32 a2, u32 a3,
                                         u32 b0, u32 b1)
{
    asm volatile(
        "mma.sync.aligned.m16n8k8.row.col.f32.tf32.tf32.f32 "
        "{%0,%1,%2,%3}, {%4,%5,%6,%7}, {%8,%9}, {%0,%1,%2,%3};"
        : "+f"(c0), "+f"(c1), "+f"(c2), "+f"(c3)
        : "r"(a0), "r"(a1), "r"(a2), "r"(a3), "r"(b0), "r"(b1));
}

// branchless insert into sorted ascending sel[0..7] (drops max; no-op if c>=sel[7])
__device__ __forceinline__ void ins_u64(u64 (&sel)[8], u64 c)
{
    u64 cur = c;
#pragma unroll
    for (int p = 0; p < 8; ++p) {
        u64 lo = (sel[p] < cur) ? sel[p] : cur;
        u64 hi = (sel[p] < cur) ? cur : sel[p];
        sel[p] = lo;
        cur = hi;
    }
}

// ========== fused encoder + conv pre-linear: 128 nodes/block ================
// Encodes (2-layer MLP) and immediately applies the shared conv linear to the
// register-resident encoded features: writes enc, lin output, and sq(enc).
template <int FIN>
__device__ __forceinline__ void enclin_body(
    const float* __restrict__ x,
    const float* __restrict__ W1, const float* __restrict__ b1,
    const float* __restrict__ W2, const float* __restrict__ b2,
    float* __restrict__ enc_out, float* __restrict__ lin_out,
    float* __restrict__ sqout, int blk, int mode,
    const float* __restrict__ convW, const float* __restrict__ convB,
    float* w1s, float* w2s, float* ws, float* b1s, float* b2s, float* bs)
{
    int tid = threadIdx.x;
    for (int i = tid; i < FIN * 32; i += 256) w1s[i] = W1[i];
    for (int i = tid; i < 1024;     i += 256) w2s[i] = W2[i];
    for (int i = tid; i < 1024;     i += 256)
        ws[i] = (mode == 0) ? (convW[i] - convW[1024 + i]) : convW[1024 + i];
    if (tid < 32) {
        b1s[tid] = b1[tid]; b2s[tid] = b2[tid];
        bs[tid] = (mode == 0) ? convB[tid] : 0.f;
    }
    __syncthreads();

    int lane = tid & 31, wid = tid >> 5;

#pragma unroll
    for (int it = 0; it < 4; ++it) {
        int nb = blk * 128 + it * 32 + wid * 4;

        float xv0 = (lane < FIN) ? x[(size_t)(nb + 0) * FIN + lane] : 0.f;
        float xv1 = (lane < FIN) ? x[(size_t)(nb + 1) * FIN + lane] : 0.f;
        float xv2 = (lane < FIN) ? x[(size_t)(nb + 2) * FIN + lane] : 0.f;
        float xv3 = (lane < FIN) ? x[(size_t)(nb + 3) * FIN + lane] : 0.f;

        float h0 = b1s[lane], h1 = h0, h2 = h0, h3 = h0;
#pragma unroll
        for (int i = 0; i < FIN; ++i) {
            float w = w1s[i * 32 + lane];
            h0 = fmaf(__shfl_sync(0xffffffffu, xv0, i), w, h0);
            h1 = fmaf(__shfl_sync(0xffffffffu, xv1, i), w, h1);
            h2 = fmaf(__shfl_sync(0xffffffffu, xv2, i), w, h2);
            h3 = fmaf(__shfl_sync(0xffffffffu, xv3, i), w, h3);
        }
        h0 = eluf(h0); h1 = eluf(h1); h2 = eluf(h2); h3 = eluf(h3);

        float o0 = b2s[lane], o1 = o0, o2 = o0, o3 = o0;
#pragma unroll
        for (int i = 0; i < 32; ++i) {
            float w = w2s[i * 32 + lane];
            o0 = fmaf(__shfl_sync(0xffffffffu, h0, i), w, o0);
            o1 = fmaf(__shfl_sync(0xffffffffu, h1, i), w, o1);
            o2 = fmaf(__shfl_sync(0xffffffffu, h2, i), w, o2);
            o3 = fmaf(__shfl_sync(0xffffffffu, h3, i), w, o3);
        }
        o0 = eluf(o0); o1 = eluf(o1); o2 = eluf(o2); o3 = eluf(o3);
        enc_out[(size_t)(nb + 0) * 32 + lane] = o0;
        enc_out[(size_t)(nb + 1) * 32 + lane] = o1;
        enc_out[(size_t)(nb + 2) * 32 + lane] = o2;
        enc_out[(size_t)(nb + 3) * 32 + lane] = o3;

        // squared norms of encoded features
        float s0 = o0 * o0, s1 = o1 * o1, s2 = o2 * o2, s3 = o3 * o3;
#pragma unroll
        for (int o = 16; o; o >>= 1) {
            s0 += __shfl_xor_sync(0xffffffffu, s0, o);
            s1 += __shfl_xor_sync(0xffffffffu, s1, o);
            s2 += __shfl_xor_sync(0xffffffffu, s2, o);
            s3 += __shfl_xor_sync(0xffffffffu, s3, o);
        }
        if (lane == 0) {
            sqout[nb + 0] = s0; sqout[nb + 1] = s1;
            sqout[nb + 2] = s2; sqout[nb + 3] = s3;
        }

        // conv linear on register-resident encoded features
        float v0 = bs[lane], v1 = v0, v2 = v0, v3 = v0;
#pragma unroll
        for (int i = 0; i < 32; ++i) {
            float w = ws[i * 32 + lane];
            v0 = fmaf(__shfl_sync(0xffffffffu, o0, i), w, v0);
            v1 = fmaf(__shfl_sync(0xffffffffu, o1, i), w, v1);
            v2 = fmaf(__shfl_sync(0xffffffffu, o2, i), w, v2);
            v3 = fmaf(__shfl_sync(0xffffffffu, o3, i), w, v3);
        }
        lin_out[(size_t)(nb + 0) * 32 + lane] = v0;
        lin_out[(size_t)(nb + 1) * 32 + lane] = v1;
        lin_out[(size_t)(nb + 2) * 32 + lane] = v2;
        lin_out[(size_t)(nb + 3) * 32 + lane] = v3;
    }
}

// grid 2176: sv(128) -> enc sv + V1 + sqV1 | trk(1024) -> enc trk + U + sqU
//          | pfc(1024) -> enc pfc + V + sqV
__global__ void __launch_bounds__(256) enclin_all_k(
    const float* x_sv, const float* x_trk, const float* x_pfc,
    const float* svW1, const float* svb1, const float* svW2, const float* svb2,
    const float* tkW1, const float* tkb1, const float* tkW2, const float* tkb2,
    const float* pfW1, const float* pfb1, const float* pfW2, const float* pfb2,
    float* o_sv, float* o_trk, float* o_pfc,
    float* V1, float* U, float* V,
    float* sqV1, float* sqU, float* sqV,
    const float* convW, const float* convB)
{
    __shared__ float w1s[1024];
    __shared__ float w2s[1024];
    __shared__ float ws[1024];
    __shared__ float b1s[32], b2s[32], bs[32];
    int b = blockIdx.x;
    if (b < 128)
        enclin_body<14>(x_sv, svW1, svb1, svW2, svb2, o_sv, V1, sqV1, b, 1,
                        convW, convB, w1s, w2s, ws, b1s, b2s, bs);
    else if (b < 1152)
        enclin_body<30>(x_trk, tkW1, tkb1, tkW2, tkb2, o_trk, U, sqU, b - 128, 0,
                        convW, convB, w1s, w2s, ws, b1s, b2s, bs);
    else
        enclin_body<10>(x_pfc, pfW1, pfb1, pfW2, pfb2, o_pfc, V, sqV, b - 1152, 1,
                        convW, convB, w1s, w2s, ws, b1s, b2s, bs);
}

// ====== fused 32x32 linear for conv3 (f1->V mode1, f2->U mode0) + sq ========
__device__ __forceinline__ void lin_body(
    const float* __restrict__ in, float* __restrict__ out,
    float* __restrict__ sqout, int blk, int mode,
    const float* __restrict__ convW, const float* __restrict__ convB,
    float* ws, float* bs)
{
    int tid = threadIdx.x;
    for (int i = tid; i < 1024; i += 256)
        ws[i] = (mode == 0) ? (convW[i] - convW[1024 + i]) : convW[1024 + i];
    if (tid < 32) bs[tid] = (mode == 0) ? convB[tid] : 0.f;
    __syncthreads();

    int lane = tid & 31, wid = tid >> 5;

#pragma unroll
    for (int it = 0; it < 4; ++it) {
        int nb = blk * 128 + it * 32 + wid * 4;

        float xv0 = in[(size_t)(nb + 0) * 32 + lane];
        float xv1 = in[(size_t)(nb + 1) * 32 + lane];
        float xv2 = in[(size_t)(nb + 2) * 32 + lane];
        float xv3 = in[(size_t)(nb + 3) * 32 + lane];

        float s0 = xv0 * xv0, s1 = xv1 * xv1, s2 = xv2 * xv2, s3 = xv3 * xv3;
#pragma unroll
        for (int o = 16; o; o >>= 1) {
            s0 += __shfl_xor_sync(0xffffffffu, s0, o);
            s1 += __shfl_xor_sync(0xffffffffu, s1, o);
            s2 += __shfl_xor_sync(0xffffffffu, s2, o);
            s3 += __shfl_xor_sync(0xffffffffu, s3, o);
        }
        if (lane == 0) {
            sqout[nb + 0] = s0; sqout[nb + 1] = s1;
            sqout[nb + 2] = s2; sqout[nb + 3] = s3;
        }

        float o0 = bs[lane], o1 = o0, o2 = o0, o3 = o0;
#pragma unroll
        for (int i = 0; i < 32; ++i) {
            float w = ws[i * 32 + lane];
            o0 = fmaf(__shfl_sync(0xffffffffu, xv0, i), w, o0);
            o1 = fmaf(__shfl_sync(0xffffffffu, xv1, i), w, o1);
            o2 = fmaf(__shfl_sync(0xffffffffu, xv2, i), w, o2);
            o3 = fmaf(__shfl_sync(0xffffffffu, xv3, i), w, o3);
        }
        out[(size_t)(nb + 0) * 32 + lane] = o0;
        out[(size_t)(nb + 1) * 32 + lane] = o1;
        out[(size_t)(nb + 2) * 32 + lane] = o2;
        out[(size_t)(nb + 3) * 32 + lane] = o3;
    }
}

__global__ void __launch_bounds__(256) lin2_k(
    const float* f1, const float* f2, float* V, float* U,
    float* sqV, float* sqU,
    const float* convW, const float* convB)
{
    __shared__ float ws[1024];
    __shared__ float bs[32];
    int b = blockIdx.x;
    if (b < 1024) lin_body(f1, V, sqV, b,        1, convW, convB, ws, bs);
    else          lin_body(f2, U, sqU, b - 1024, 0, convW, convB, ws, bs);
}

// ================= kNN: mma scoring + running-tau selection =================
// Proven R13 configuration (stride-66 scalar selection, conflict-free), with
// running-tau threshold and branchless inserts. Two work-sets per launch so
// conv1 (Ns=64) and conv2 (Ns=512) share one grid (long blocks first).
#define CH       64
#define SSTRIDE  66
#define C4STRIDE 66      /* float4 units per c4sel slot */
#define CAPK     10
#define SM_SCORES 0
#define SM_HILO  33792   /* 16 slots x 66 float4 = 16896 B */
#define SM_SQS   50688
#define SM_SDS   50944
#define SM_TAU   51456
#define SM_BUF   51968
#define KNN_SMEM (SM_BUF + 256 * CAPK * 8)   /* 72448 */

__device__ __forceinline__ void flush_u64(const u64* mybuf, int& cnt, u64 (&sel)[8])
{
    for (int i = 0; i < cnt; ++i)
        ins_u64(sel, mybuf[i]);
    cnt = 0;
}

__global__ void __launch_bounds__(256, 3) knn_k(
                      const float* __restrict__ srcA, const float* __restrict__ sqsrcA,
                      const float* __restrict__ VA,   float* __restrict__ outA, int NsA,
                      const float* __restrict__ srcB, const float* __restrict__ sqsrcB,
                      const float* __restrict__ VB,   float* __restrict__ outB, int NsB,
                      int nblkA,
                      const float* __restrict__ dst_enc,
                      const float* __restrict__ sq_dst,
                      const float* __restrict__ U)
{
    extern __shared__ char smraw[];
    float*  scores = (float*)(smraw + SM_SCORES);  // [128][66]
    float4* hi4    = (float4*)(smraw + SM_HILO);   // [8][66] hi, then [8][66] lo
    float*  hifl   = (float*)(smraw + SM_HILO);
    float*  sqs    = (float*)(smraw + SM_SQS);     // [64]
    float*  sds    = (float*)(smraw + SM_SDS);     // [128]
    float*  tau    = (float*)(smraw + SM_TAU);     // [128]
    u64*    buf    = (u64*)(smraw + SM_BUF);       // [256][CAPK]
    int*    idxs   = (int*)(smraw + SM_HILO);      // overlay after last MMA

    int bid = blockIdx.x;
    const float* src_enc; const float* sq_src; const float* V; float* out; int Ns;
    if (bid < nblkA) {
        src_enc = srcA; sq_src = sqsrcA; V = VA; out = outA; Ns = NsA;
    } else {
        bid -= nblkA;
        src_enc = srcB; sq_src = sqsrcB; V = VB; out = outB; Ns = NsB;
    }

    int tid  = threadIdx.x;
    int lane = tid & 31;
    int w    = tid >> 5;          // 0..7
    int e    = bid >> 2;
    int quar = bid & 3;
    int g    = lane >> 2;         // 0..7
    int c4   = lane & 3;          // 0..3

    const float* sbase = src_enc + (size_t)e * Ns * 32;
    int dstblk = quar * 128;
    const float* dbase = dst_enc + ((size_t)e * 512 + dstblk + w * 16) * 32;

    if (tid < 128) sds[tid] = sq_dst[(size_t)e * 512 + dstblk + tid];

    // ---- A fragments: one m16 tile (16 dsts) per warp ----
    u32 ahi[16], alo[16];
#pragma unroll
    for (int j = 0; j < 4; ++j) {
        int k = 8 * j + c4;
        tf32split(dbase[g * 32 + k],           ahi[4*j+0], alo[4*j+0]);
        tf32split(dbase[(g + 8) * 32 + k],     ahi[4*j+1], alo[4*j+1]);
        tf32split(dbase[g * 32 + k + 4],       ahi[4*j+2], alo[4*j+2]);
        tf32split(dbase[(g + 8) * 32 + k + 4], ahi[4*j+3], alo[4*j+3]);
    }
    __syncthreads();

    float sd0 = sds[w * 16 + g];
    float sd1 = sds[w * 16 + 8 + g];
    int rowA0 = (w * 16 + g) * SSTRIDE;
    int rowA1 = (w * 16 + 8 + g) * SSTRIDE;

    int myd = tid >> 1;
    int hh  = tid & 1;
    int selrow = myd * SSTRIDE;

    const float4* bhA = hi4 + (size_t)c4 * C4STRIDE;
    const float4* bhB = hi4 + (size_t)(c4 + 4) * C4STRIDE;
    const float4* blA = bhA + 8 * C4STRIDE;
    const float4* blB = bhB + 8 * C4STRIDE;

    u64 sel[8];
#pragma unroll
    for (int k = 0; k < 8; ++k) sel[k] = ~0ull;
    int cnt = 0;
    u64 trun = ~0ull;
    u64* mybuf = buf + (size_t)tid * CAPK;
    unsigned buf_sa = (unsigned)__cvta_generic_to_shared(mybuf);

    int stg = (lane & 7) * (C4STRIDE * 4) + (lane >> 3);

    int nch = (Ns + CH - 1) / CH;
    for (int ch = 0; ch < nch; ++ch) {
        int cbase = ch * CH;

        __syncthreads();
        for (int sl = w; sl < CH; sl += 8) {
            float x = sbase[(size_t)(cbase + sl) * 32 + lane];
            u32 h, l;
            tf32split(x, h, l);
            hifl[stg + sl * 4]                    = __uint_as_float(h);
            hifl[stg + sl * 4 + 8 * C4STRIDE * 4] = __uint_as_float(l);
        }
        if (tid < CH) sqs[tid] = sq_src[(size_t)e * Ns + cbase + tid];
        __syncthreads();

        // ---- MMA + epilogue: 3 independent chains, scores + subset minima --
        float mn00 = 3.4e38f, mn01 = 3.4e38f, mn10 = 3.4e38f, mn11 = 3.4e38f;
#pragma unroll
        for (int st = 0; st < CH / 8; ++st) {
            int sl0 = st << 3;
            int fidx = sl0 + g;
            float4 H0 = bhA[fidx];
            float4 H1 = bhB[fidx];
            float4 L0 = blA[fidx];
            float4 L1 = blB[fidx];

            float p0 = 0.f, p1 = 0.f, p2 = 0.f, p3 = 0.f;
            float q0 = 0.f, q1 = 0.f, q2 = 0.f, q3 = 0.f;
            float r0 = 0.f, r1 = 0.f, r2 = 0.f, r3 = 0.f;

            mma_tf32(p0, p1, p2, p3, ahi[0],  ahi[1],  ahi[2],  ahi[3],
                     __float_as_uint(H0.x), __float_as_uint(H1.x));
            mma_tf32(p0, p1, p2, p3, ahi[4],  ahi[5],  ahi[6],  ahi[7],
                     __float_as_uint(H0.y), __float_as_uint(H1.y));
            mma_tf32(p0, p1, p2, p3, ahi[8],  ahi[9],  ahi[10], ahi[11],
                     __float_as_uint(H0.z), __float_as_uint(H1.z));
            mma_tf32(p0, p1, p2, p3, ahi[12], ahi[13], ahi[14], ahi[15],
                     __float_as_uint(H0.w), __float_as_uint(H1.w));
            mma_tf32(q0, q1, q2, q3, ahi[0],  ahi[1],  ahi[2],  ahi[3],
                     __float_as_uint(L0.x), __float_as_uint(L1.x));
            mma_tf32(q0, q1, q2, q3, ahi[4],  ahi[5],  ahi[6],  ahi[7],
                     __float_as_uint(L0.y), __float_as_uint(L1.y));
            mma_tf32(q0, q1, q2, q3, ahi[8],  ahi[9],  ahi[10], ahi[11],
                     __float_as_uint(L0.z), __float_as_uint(L1.z));
            mma_tf32(q0, q1, q2, q3, ahi[12], ahi[13], ahi[14], ahi[15],
                     __float_as_uint(L0.w), __float_as_uint(L1.w));
            mma_tf32(r0, r1, r2, r3, alo[0],  alo[1],  alo[2],  alo[3],
                     __float_as_uint(H0.x), __float_as_uint(H1.x));
            mma_tf32(r0, r1, r2, r3, alo[4],  alo[5],  alo[6],  alo[7],
                     __float_as_uint(H0.y), __float_as_uint(H1.y));
            mma_tf32(r0, r1, r2, r3, alo[8],  alo[9],  alo[10], alo[11],
                     __float_as_uint(H0.z), __float_as_uint(H1.z));
            mma_tf32(r0, r1, r2, r3, alo[12], alo[13], alo[14], alo[15],
                     __float_as_uint(H0.w), __float_as_uint(H1.w));

            float a0 = p0 + (q0 + r0);
            float a1 = p1 + (q1 + r1);
            float a2 = p2 + (q2 + r2);
            float a3 = p3 + (q3 + r3);

            float2 sqp = *(const float2*)(sqs + sl0 + 2 * c4);
            int col = sl0 + 2 * c4;
            float d00 = fmaxf(fmaf(-2.f, a0, sd0 + sqp.x), 0.f);
            float d01 = fmaxf(fmaf(-2.f, a1, sd0 + sqp.y), 0.f);
            float d10 = fmaxf(fmaf(-2.f, a2, sd1 + sqp.x), 0.f);
            float d11 = fmaxf(fmaf(-2.f, a3, sd1 + sqp.y), 0.f);
            mn00 = fminf(mn00, d00); mn01 = fminf(mn01, d01);
            mn10 = fminf(mn10, d10); mn11 = fminf(mn11, d11);
            *(float2*)(scores + rowA0 + col) = make_float2(d00, d01);
            *(float2*)(scores + rowA1 + col) = make_float2(d10, d11);
        }
        {
            float m0 = fmaxf(mn00, mn01);
            m0 = fmaxf(m0, __shfl_xor_sync(0xffffffffu, m0, 1));
            m0 = fmaxf(m0, __shfl_xor_sync(0xffffffffu, m0, 2));
            float m1 = fmaxf(mn10, mn11);
            m1 = fmaxf(m1, __shfl_xor_sync(0xffffffffu, m1, 1));
            m1 = fmaxf(m1, __shfl_xor_sync(0xffffffffu, m1, 2));
            if (c4 == 0) {
                tau[w * 16 + g]     = m0;
                tau[w * 16 + 8 + g] = m1;
            }
        }
        __syncthreads();

        // ---- selection: running-tau threshold, predicated appends ----
        {
            u64 tu = ((u64)(__float_as_uint(tau[myd]) + 1u)) << 32;
            trun = (tu < trun) ? tu : trun;
            u64 t = (trun < sel[7]) ? trun : sel[7];

            for (int cg = 0; cg < 32; cg += 4) {
                int c0i = 2 * cg + hh;
                float v0 = scores[selrow + c0i];
                float v1 = scores[selrow + c0i + 2];
                float v2 = scores[selrow + c0i + 4];
                float v3 = scores[selrow + c0i + 6];
                u64 p0 = ((u64)__float_as_uint(v0) << 32) | (u32)(cbase + c0i);
                u64 p1 = ((u64)__float_as_uint(v1) << 32) | (u32)(cbase + c0i + 2);
                u64 p2 = ((u64)__float_as_uint(v2) << 32) | (u32)(cbase + c0i + 4);
                u64 p3 = ((u64)__float_as_uint(v3) << 32) | (u32)(cbase + c0i + 6);

                asm volatile("{.reg .pred p; setp.lt.u64 p, %1, %2; @p st.shared.b64 [%0], %1;}"
                    :: "r"(buf_sa + (unsigned)cnt * 8u), "l"(p0), "l"(t) : "memory");
                cnt += (p0 < t) ? 1 : 0;
                asm volatile("{.reg .pred p; setp.lt.u64 p, %1, %2; @p st.shared.b64 [%0], %1;}"
                    :: "r"(buf_sa + (unsigned)cnt * 8u), "l"(p1), "l"(t) : "memory");
                cnt += (p1 < t) ? 1 : 0;
                asm volatile("{.reg .pred p; setp.lt.u64 p, %1, %2; @p st.shared.b64 [%0], %1;}"
                    :: "r"(buf_sa + (unsigned)cnt * 8u), "l"(p2), "l"(t) : "memory");
                cnt += (p2 < t) ? 1 : 0;
                asm volatile("{.reg .pred p; setp.lt.u64 p, %1, %2; @p st.shared.b64 [%0], %1;}"
                    :: "r"(buf_sa + (unsigned)cnt * 8u), "l"(p3), "l"(t) : "memory");
                cnt += (p3 < t) ? 1 : 0;

                if (__any_sync(0xffffffffu, cnt >= CAPK - 4)) {
                    flush_u64(mybuf, cnt, sel);
                    t = (trun < sel[7]) ? trun : sel[7];
                }
            }
        }
    }
    flush_u64(mybuf, cnt, sel);

    // ---- dump per-thread lists, 2-way exact merge ----
#pragma unroll
    for (int k = 0; k < 8; ++k) mybuf[k] = sel[k];
    __syncthreads();

    if (tid < 128) {
        u64 m[8];
        const u64* l0 = buf + (size_t)(2 * tid) * CAPK;
        const u64* l1 = buf + (size_t)(2 * tid + 1) * CAPK;
#pragma unroll
        for (int k = 0; k < 8; ++k) m[k] = l0[k];
#pragma unroll
        for (int k = 0; k < 8; ++k)
            ins_u64(m, l1[k]);
#pragma unroll
        for (int k = 0; k < 8; ++k)
            idxs[tid * 8 + k] = (int)(u32)m[k];
    }
    __syncthreads();

    // ---- aggregation: warp per dst, coalesced V gathers ----
    const float* Ve = V + (size_t)e * Ns * 32;
    for (int dd = w; dd < 128; dd += 8) {
        int dg = e * 512 + dstblk + dd;
        float mx = -3.4e38f;
#pragma unroll
        for (int k = 0; k < KNN; ++k) {
            int s = idxs[dd * 8 + k];
            mx = fmaxf(mx, Ve[s * 32 + lane]);
        }
        out[(size_t)dg * 32 + lane] = eluf(U[(size_t)dg * 32 + lane] + mx);
    }
}

// ---------------- mean pool + head MLP + sigmoid -----------------------------
__global__ void pool_k(const float* __restrict__ f3,
                       const float* __restrict__ W1, const float* __restrict__ b1,
                       const float* __restrict__ W2, const float* __restrict__ b2,
                       float* __restrict__ out, int out_size)
{
    int e = blockIdx.x;
    int tid = threadIdx.x;
    int j = tid & 31, g = tid >> 5;
    const float* base = f3 + (size_t)e * 512 * 32;
    float acc = 0.f;
    for (int r = g; r < 512; r += 8) acc += base[r * 32 + j];
    __shared__ float red[8][32];
    red[g][j] = acc;
    __syncthreads();
    if (tid < 32) {
        float s = 0.f;
#pragma unroll
        for (int gg = 0; gg < 8; ++gg) s += red[gg][tid];
        float pooled = s * (1.f / 512.f);
        float h = b1[tid];
#pragma unroll
        for (int i = 0; i < 32; ++i)
            h = fmaf(__shfl_sync(0xffffffffu, pooled, i), W1[i * 32 + tid], h);
        h = eluf(h);
        float t = h * W2[tid];
#pragma unroll
        for (int o = 16; o; o >>= 1) t += __shfl_down_sync(0xffffffffu, t, o);
        if (tid == 0) {
            float prob = 1.f / (1.f + expf(-(t + b2[0])));
            out[e] = prob;
            if (out_size == 2 * BB) out[BB + e] = (float)e;
            else if (out_size == 3 * BB) ((long long*)(out + BB))[e] = (long long)e;
        }
    }
}

// ---------------- launch ------------------------------------------------------
extern "C" void kernel_launch(void* const* d_in, const int* in_sizes, int n_in,
                              void* d_out, int out_size)
{
    const float* x_sv   = (const float*)d_in[0];
    const float* x_trk  = (const float*)d_in[1];
    const float* x_pfc  = (const float*)d_in[2];
    const float* sv_W1  = (const float*)d_in[6];
    const float* sv_b1  = (const float*)d_in[7];
    const float* sv_W2  = (const float*)d_in[8];
    const float* sv_b2  = (const float*)d_in[9];
    const float* trk_W1 = (const float*)d_in[10];
    const float* trk_b1 = (const float*)d_in[11];
    const float* trk_W2 = (const float*)d_in[12];
    const float* trk_b2 = (const float*)d_in[13];
    const float* pfc_W1 = (const float*)d_in[14];
    const float* pfc_b1 = (const float*)d_in[15];
    const float* pfc_W2 = (const float*)d_in[16];
    const float* pfc_b2 = (const float*)d_in[17];
    const float* conv_W = (const float*)d_in[18];
    const float* conv_b = (const float*)d_in[19];
    const float* out_W1 = (const float*)d_in[20];
    const float* out_b1 = (const float*)d_in[21];
    const float* out_W2 = (const float*)d_in[22];
    const float* out_b2 = (const float*)d_in[23];
    float* out = (float*)d_out;

    float *sv, *trk, *pfc, *U, *V, *V1, *f1, *f2, *f3, *sqV1, *sqV, *sqU;
    cudaGetSymbolAddress((void**)&sv,  g_sv);
    cudaGetSymbolAddress((void**)&trk, g_trk);
    cudaGetSymbolAddress((void**)&pfc, g_pfc);
    cudaGetSymbolAddress((void**)&U,   g_U);
    cudaGetSymbolAddress((void**)&V,   g_V);
    cudaGetSymbolAddress((void**)&V1,  g_V1);
    cudaGetSymbolAddress((void**)&f1,  g_f1);
    cudaGetSymbolAddress((void**)&f2,  g_f2);
    cudaGetSymbolAddress((void**)&f3,  g_f3);
    cudaGetSymbolAddress((void**)&sqV1, g_sqV1);
    cudaGetSymbolAddress((void**)&sqV,  g_sqV);
    cudaGetSymbolAddress((void**)&sqU,  g_sqU);

    cudaFuncSetAttribute(knn_k, cudaFuncAttributeMaxDynamicSharedMemorySize, KNN_SMEM);

    // 1: fused encoders + conv pre-linears (enc, V1/U/V, sq)
    enclin_all_k<<<2176, 256>>>(x_sv, x_trk, x_pfc,
                                sv_W1, sv_b1, sv_W2, sv_b2,
                                trk_W1, trk_b1, trk_W2, trk_b2,
                                pfc_W1, pfc_b1, pfc_W2, pfc_b2,
                                sv, trk, pfc,
                                V1, U, V, sqV1, sqU, sqV,
                                conv_W, conv_b);
    // 2: fused conv1 + conv2 kNN (long conv2 blocks first)
    knn_k<<<2048, 256, KNN_SMEM>>>(pfc, sqV, V, f2, N_PFC,
                                   sv, sqV1, V1, f1, N_SV,
                                   1024, trk, sqU, U);
    // 3: conv3 pre-linears
    lin2_k<<<2048, 256>>>(f1, f2, V, U, sqV, sqU, conv_W, conv_b);
    // 4: conv3 kNN (f1 -> f2)
    knn_k<<<1024, 256, KNN_SMEM>>>(f1, sqV, V, f3, N_TRK,
                                   f1, sqV, V, f3, N_TRK,
                                   1024, f2, sqU, U);
    // 5: pool + head
    pool_k<<<BB, 256>>>(f3, out_W1, out_b1, out_W2, out_b2, out, out_size);
}